// round 16
// baseline (speedup 1.0000x reference)
#include <cuda_runtime.h>
#include <cstdint>
#include <math.h>

#define IN_DIM 256
#define HIDDEN 64
#define MAX_NODES 100000
#define NT1 512      // k1 block size
#define NT2 256      // persistent tail block size

// Pipeline state (allocation-free: __device__ globals)
__device__ float g_wv[IN_DIM];        // W @ w2 (computed once in init)
__device__ float g_cst;               // b.w2 + b2
__device__ float g_z[MAX_NODES];      // x @ wv
__device__ float g_zs[MAX_NODES];     // dinv * z
__device__ float g_dinv[MAX_NODES];   // (deg+1)^-1/2
__device__ float g_aggs[MAX_NODES];   // SUM of zs[s] over in-edges (unscaled)
__device__ int   g_degcnt[MAX_NODES]; // zeroed via cudaMemsetAsync
__device__ int   g_stride;            // 1 = int32 edge_index, 2 = int64

// Software grid barrier (generation counter; survives graph replays)
__device__ unsigned g_count;
__device__ volatile unsigned g_gen;

__device__ __forceinline__ void gbar(unsigned nb) {
    __syncthreads();
    if (threadIdx.x == 0) {
        __threadfence();
        unsigned gen = g_gen;
        if (atomicAdd(&g_count, 1u) == nb - 1) {
            g_count = 0;
            __threadfence();
            g_gen = gen + 1;
        } else {
            while (g_gen == gen) { __nanosleep(64); }
        }
        __threadfence();
    }
    __syncthreads();
}

// ---------------------------------------------------------------------------
// init (1 block): wv = W@w2, cst = b.w2+b2, dtype probe.
// ---------------------------------------------------------------------------
__global__ void init_kernel(const int* __restrict__ ei, const float* __restrict__ W,
                            const float* __restrict__ b, const float* __restrict__ w2,
                            const float* __restrict__ b2) {
    int k = threadIdx.x;
    float s = 0.0f;
    #pragma unroll 8
    for (int j = 0; j < HIDDEN; j++) s = fmaf(W[k * HIDDEN + j], w2[j], s);
    g_wv[k] = s;
    if (k == 0) {
        float c = b2[0];
        for (int j = 0; j < HIDDEN; j++) c = fmaf(b[j], w2[j], c);
        g_cst = c;
        int nz = 0;   // int64 LE (<2^31): odd 32-bit words all zero
        #pragma unroll
        for (int i = 1; i < 128; i += 2) nz |= ei[i];
        g_stride = (nz == 0) ? 2 : 1;
    }
}

// ---------------------------------------------------------------------------
// k1 (full width): z = x@wv (warp/row, DRAM-bound) + degree histogram
// (LTS-atomic-bound) + zero aggs. Disjoint resources -> overlap inside kernel.
// ---------------------------------------------------------------------------
__global__ void __launch_bounds__(NT1)
k1(const float* __restrict__ x, const int* __restrict__ ei, int n, int E) {
    __shared__ float4 swv[IN_DIM / 4];
    const int tid  = threadIdx.x;
    const int nth  = gridDim.x * NT1;
    const int gtid = blockIdx.x * NT1 + tid;

    if (tid < IN_DIM / 4)
        swv[tid] = reinterpret_cast<const float4*>(g_wv)[tid];
    for (int i = gtid; i < n; i += nth) g_aggs[i] = 0.0f;   // consumed only later
    __syncthreads();
    const int st = g_stride;

    // ---- z matvec: warp per row, 2x float4 per lane (coalesced) ----
    {
        const int lane = tid & 31;
        const int row = blockIdx.x * 16 + (tid >> 5);
        if (row < n) {
            float4 w0 = swv[lane], w1 = swv[lane + 32];
            const float4* xr = reinterpret_cast<const float4*>(x + (size_t)row * IN_DIM);
            float4 a = xr[lane], c = xr[lane + 32];
            float p = a.x * w0.x + a.y * w0.y + a.z * w0.z + a.w * w0.w
                    + c.x * w1.x + c.y * w1.y + c.z * w1.z + c.w * w1.w;
            #pragma unroll
            for (int o = 16; o; o >>= 1) p += __shfl_xor_sync(0xffffffffu, p, o);
            if (lane == 0) g_z[row] = p;
        }
    }

    // ---- degree histogram over dst row ----
    if (st == 1) {
        const int4* d4p = reinterpret_cast<const int4*>(ei + E);
        int nc = E >> 2;
        for (int c = gtid; c < nc; c += nth) {
            int4 d4 = d4p[c];
            atomicAdd(&g_degcnt[d4.x], 1);
            atomicAdd(&g_degcnt[d4.y], 1);
            atomicAdd(&g_degcnt[d4.z], 1);
            atomicAdd(&g_degcnt[d4.w], 1);
        }
        for (int e = (nc << 2) + gtid; e < E; e += nth)
            atomicAdd(&g_degcnt[ei[E + e]], 1);
    } else {
        for (int e = gtid; e < E; e += nth)
            atomicAdd(&g_degcnt[ei[(size_t)2 * (E + e)]], 1);
    }
}

// ---------------------------------------------------------------------------
// k234 (persistent at QUERIED occupancy, nb co-resident blocks):
//   dinv/zs  -> gbar ->  scatter aggs[d] += zs[s]  -> gbar ->  sigmoid out
// ---------------------------------------------------------------------------
__global__ void __launch_bounds__(NT2, 6)
k234(const int* __restrict__ ei, float* __restrict__ out, int n, int E, int nb) {
    const int tid  = threadIdx.x;
    const int gtid = blockIdx.x * NT2 + tid;
    const int nth  = nb * NT2;
    const int st   = g_stride;

    // ---- phase 0: dinv = rsqrt(deg+1); zs = dinv*z ----
    for (int i = gtid; i < n; i += nth) {
        float dv = rsqrtf((float)g_degcnt[i] + 1.0f);
        g_dinv[i] = dv;
        g_zs[i] = dv * g_z[i];
    }
    gbar(nb);

    // ---- phase 1: scatter (int4 chunks: 4 independent gathers in flight) ----
    if (st == 1) {
        const int4* s4p = reinterpret_cast<const int4*>(ei);
        const int4* d4p = reinterpret_cast<const int4*>(ei + E);
        int nc = E >> 2;
        for (int c = gtid; c < nc; c += nth) {
            int4 s4 = s4p[c];
            int4 d4 = d4p[c];
            float v0 = g_zs[s4.x], v1 = g_zs[s4.y];
            float v2 = g_zs[s4.z], v3 = g_zs[s4.w];
            atomicAdd(&g_aggs[d4.x], v0);
            atomicAdd(&g_aggs[d4.y], v1);
            atomicAdd(&g_aggs[d4.z], v2);
            atomicAdd(&g_aggs[d4.w], v3);
        }
        for (int e = (nc << 2) + gtid; e < E; e += nth)
            atomicAdd(&g_aggs[ei[E + e]], g_zs[ei[e]]);
    } else {
        for (int e = gtid; e < E; e += nth) {
            int s = ei[(size_t)2 * e];
            int d = ei[(size_t)2 * (E + e)];
            atomicAdd(&g_aggs[d], g_zs[s]);
        }
    }
    gbar(nb);

    // ---- phase 2: out = sigmoid( dinv*(aggs + zs) + cst ) ----
    const float cst = g_cst;
    for (int i = gtid; i < n; i += nth) {
        float zv = g_dinv[i] * (g_aggs[i] + g_zs[i]) + cst;
        out[i] = 1.0f / (1.0f + __expf(-zv));
    }
}

// ---------------------------------------------------------------------------
extern "C" void kernel_launch(void* const* d_in, const int* in_sizes, int n_in,
                              void* d_out, int out_size) {
    const float* x  = (const float*)d_in[0];
    const int*   ei = (const int*)d_in[1];      // int32 words (or int64 pairs)
    const float* W  = (const float*)d_in[2];
    const float* b  = (const float*)d_in[3];
    const float* w2 = (const float*)d_in[4];
    const float* b2 = (const float*)d_in[5];
    float* out = (float*)d_out;

    int n = in_sizes[0] / IN_DIM;     // 100000
    int E = in_sizes[1] / 2;          // 1600000 elements per row

    // Co-residency-safe persistent grid: SMs x max-active-blocks (host query,
    // capture-legal, deterministic across replays).
    static int nb = 0;
    if (nb == 0) {
        int dev = 0, sms = 148, mab = 1;
        cudaGetDevice(&dev);
        cudaDeviceGetAttribute(&sms, cudaDevAttrMultiProcessorCount, dev);
        cudaOccupancyMaxActiveBlocksPerMultiprocessor(&mab, k234, NT2, 0);
        if (mab < 1) mab = 1;
        nb = sms * mab;
    }

    void* degp = nullptr;
    cudaGetSymbolAddress(&degp, g_degcnt);
    cudaMemsetAsync(degp, 0, (size_t)n * sizeof(int));

    init_kernel<<<1, 256>>>(ei, W, b, w2, b2);
    k1<<<(n + 15) / 16, NT1>>>(x, ei, n, E);
    k234<<<nb, NT2>>>(ei, out, n, E, nb);
}